// round 16
// baseline (speedup 1.0000x reference)
#include <cuda_runtime.h>

#define BB 512
#define NN 128
#define DD 256
#define TT 512
#define NP (NN + 4)    // padded fp32 row stride for S
#define XPR 36         // u64 row stride for pair region (32 + 4 pad)
#define XAR 72         // u32 view row stride of same region

typedef unsigned int u32t;
typedef unsigned long long u64t;

// round fp32 -> tf32 (u32 bit pattern, fp32-compatible)
__device__ __forceinline__ u32t tf32h(float v) {
    u32t h; asm("cvt.rna.tf32.f32 %0, %1;" : "=r"(h) : "f"(v)); return h;
}
// split fp32 into tf32 hi + tf32 lo
__device__ __forceinline__ void split_tf32(float v, u32t& hi, u32t& lo) {
    u32t h; asm("cvt.rna.tf32.f32 %0, %1;" : "=r"(h) : "f"(v));
    float rem = v - __uint_as_float(h);
    u32t l; asm("cvt.rna.tf32.f32 %0, %1;" : "=r"(l) : "f"(rem));
    hi = h; lo = l;
}

__device__ __forceinline__ void mma8(float& d0, float& d1, float& d2, float& d3,
                                     u32t a0, u32t a1, u32t a2, u32t a3,
                                     u32t b0, u32t b1) {
    asm volatile("mma.sync.aligned.m16n8k8.row.col.f32.tf32.tf32.f32 "
        "{%0,%1,%2,%3}, {%4,%5,%6,%7}, {%8,%9}, {%0,%1,%2,%3};"
        : "+f"(d0), "+f"(d1), "+f"(d2), "+f"(d3)
        : "r"(a0), "r"(a1), "r"(a2), "r"(a3), "r"(b0), "r"(b1));
}

struct Smem {
    float S[NN][NP];        // assignment matrix S, fp32     (67.6 KB)
    u64t  Xp[NN][XPR];      // pair region / u32 tf32 region (36.9 KB)
    float w[DD];
    float outv[NN];
    float dis[NN];
    float rfac[NN];
    float tvec[NN];
    float alpha[NN];
    float colfac[NN];
    unsigned int bits[4];
    float cutv;
    int   kidx;
    int   nuniq;
};

__global__ __launch_bounds__(256, 2)
void graph_coarsen_kernel(const float* __restrict__ x,
                          const float* __restrict__ adj,
                          const int*   __restrict__ head,
                          const float* __restrict__ lw,
                          const float* __restrict__ bias,
                          float* __restrict__ emb,
                          float* __restrict__ nadj)
{
    extern __shared__ char smraw[];
    Smem& sm = *reinterpret_cast<Smem*>(smraw);
    u32t* Xa = reinterpret_cast<u32t*>(&sm.Xp[0][0]);   // u32 view, stride XAR

    const int b    = blockIdx.x;
    const int tid  = threadIdx.x;
    const int lane = tid & 31;
    const int wid  = tid >> 5;

    const float* adjB = adj + (size_t)b * NN * NN;
    const float* xB   = x   + (size_t)b * NN * DD;

    sm.w[tid] = lw[tid];
    if (tid < 4) sm.bits[tid] = 0u;
    __syncthreads();

    // ---- out[n] = x[n,:] . w ----
    for (int n = wid; n < NN; n += 8) {
        const float* xr = xB + n * DD;
        float s = 0.f;
        #pragma unroll
        for (int t = 0; t < DD / 32; ++t)
            s = fmaf(xr[lane + 32 * t], sm.w[lane + 32 * t], s);
        #pragma unroll
        for (int o = 16; o > 0; o >>= 1) s += __shfl_down_sync(0xffffffffu, s, o);
        if (lane == 0) sm.outv[n] = s;
    }
    // ---- degree / dis / mask ----
    for (int i = wid; i < NN; i += 8) {
        const float* ar = adjB + i * NN;
        float s = 0.f;
        #pragma unroll
        for (int t = 0; t < NN / 32; ++t) s += ar[lane + 32 * t];
        #pragma unroll
        for (int o = 16; o > 0; o >>= 1) s += __shfl_down_sync(0xffffffffu, s, o);
        if (lane == 0) {
            float deg = s + 1.0f;
            float dv  = rsqrtf(fmaxf(deg, 1.0f));
            sm.dis[i]  = dv;
            sm.rfac[i] = (s > 0.f) ? dv : 0.f;
        }
    }
    __syncthreads();

    if (tid < NN) sm.tvec[tid] = sm.dis[tid] * sm.outv[tid];
    {
        int v0 = head[(size_t)b * TT + tid];
        int v1 = head[(size_t)b * TT + 256 + tid];
        atomicOr(&sm.bits[v0 >> 5], 1u << (v0 & 31));
        atomicOr(&sm.bits[v1 >> 5], 1u << (v1 & 31));
    }
    __syncthreads();

    // ---- o2 = norm_adj @ out + bias ; alpha = sigmoid(o2^2) ----
    {
        const float biasv = bias[0];
        for (int i = wid; i < NN; i += 8) {
            const float* ar = adjB + i * NN;
            float s = 0.f;
            #pragma unroll
            for (int t = 0; t < NN / 32; ++t)
                s = fmaf(ar[lane + 32 * t], sm.tvec[lane + 32 * t], s);
            #pragma unroll
            for (int o = 16; o > 0; o >>= 1) s += __shfl_down_sync(0xffffffffu, s, o);
            if (lane == 0) {
                float o2 = fmaf(sm.rfac[i], s + sm.tvec[i], biasv);
                float q  = o2 * o2;
                sm.alpha[i] = 1.0f / (1.0f + expf(-q));
            }
        }
    }
    if (tid == 0) {
        int nu = __popc(sm.bits[0]) + __popc(sm.bits[1]) +
                 __popc(sm.bits[2]) + __popc(sm.bits[3]);
        sm.nuniq = nu;
        int k   = (int)ceilf((float)nu * 0.1f) + 1;
        int idx = k - 1;
        if (idx < 0) idx = 0;
        if (idx > NN - 1) idx = NN - 1;
        sm.kidx = idx;
    }
    __syncthreads();

    if (tid < NN) {
        float ai = sm.alpha[tid];
        int cnt = 0;
        #pragma unroll 8
        for (int j = 0; j < NN; ++j) {
            float aj = sm.alpha[j];
            cnt += (aj > ai) || (aj == ai && j < tid);
        }
        if (cnt == sm.kidx) sm.cutv = (sm.nuniq > 1) ? ai : 0.f;
    }
    __syncthreads();
    if (tid < NN) {
        float ca = fmaxf(sm.alpha[tid] + 1e-7f - sm.cutv, 0.f);
        sm.colfac[tid] = sm.dis[tid] * ca;
    }
    __syncthreads();

    // ---- build S (fp32) ----
    for (int i = wid; i < NN; i += 8) {
        const float* ar = adjB + i * NN;
        float v[NN / 32];
        float s = 0.f;
        #pragma unroll
        for (int t = 0; t < NN / 32; ++t) {
            int j = lane + 32 * t;
            float a = ar[j] + ((j == i) ? 1.f : 0.f);
            v[t] = a * sm.colfac[j];
            s += v[t];
        }
        #pragma unroll
        for (int o = 16; o > 0; o >>= 1) s += __shfl_down_sync(0xffffffffu, s, o);
        s = __shfl_sync(0xffffffffu, s, 0);
        float rf  = sm.rfac[i];
        float tot = rf * s;
        float r2  = rf / fmaxf(tot, 1e-12f);
        #pragma unroll
        for (int t = 0; t < NN / 32; ++t)
            sm.S[i][lane + 32 * t] = r2 * v[t];
    }

    const int r8 = lane >> 2;        // 0..7
    const int c4 = lane & 3;         // 0..3
    const int m0 = wid * 16;         // warp's 16-row output strip

    // ========== GEMM1: emb = S^T @ x, 8 chunks of 32 d-cols ==========
    // A = S (split hi/lo on the fly), B = x pre-split pairs in smem.
    {
        float* embB = emb + (size_t)b * NN * DD;
        for (int dc = 0; dc < 8; ++dc) {
            const int d0 = dc * 32;
            __syncthreads();      // prior readers of Xp done
            #pragma unroll
            for (int i = 0; i < 4; ++i) {          // stage pairs
                int q   = tid + 256 * i;
                int row = q >> 3, cc = (q & 7) * 4;
                float4 v = *reinterpret_cast<const float4*>(&xB[row * DD + d0 + cc]);
                u32t h0,l0,h1,l1,h2,l2,h3,l3;
                split_tf32(v.x, h0, l0); split_tf32(v.y, h1, l1);
                split_tf32(v.z, h2, l2); split_tf32(v.w, h3, l3);
                *reinterpret_cast<uint4*>(&sm.Xp[row][cc])     = make_uint4(h0, l0, h1, l1);
                *reinterpret_cast<uint4*>(&sm.Xp[row][cc + 2]) = make_uint4(h2, l2, h3, l3);
            }
            __syncthreads();

            float C[4][4];
            #pragma unroll
            for (int nt = 0; nt < 4; ++nt)
                #pragma unroll
                for (int q = 0; q < 4; ++q) C[nt][q] = 0.f;

            for (int k8 = 0; k8 < 16; ++k8) {
                const int k0 = k8 * 8;
                u32t Ah[4], Al[4];
                split_tf32(sm.S[k0 + c4][m0 + r8],         Ah[0], Al[0]);
                split_tf32(sm.S[k0 + c4][m0 + r8 + 8],     Ah[1], Al[1]);
                split_tf32(sm.S[k0 + c4 + 4][m0 + r8],     Ah[2], Al[2]);
                split_tf32(sm.S[k0 + c4 + 4][m0 + r8 + 8], Ah[3], Al[3]);
                #pragma unroll
                for (int nt = 0; nt < 4; ++nt) {
                    int n = nt * 8 + r8;
                    u64t p0 = sm.Xp[k0 + c4][n];
                    u64t p1 = sm.Xp[k0 + c4 + 4][n];
                    u32t Bh0 = (u32t)p0, Bl0 = (u32t)(p0 >> 32);
                    u32t Bh1 = (u32t)p1, Bl1 = (u32t)(p1 >> 32);
                    mma8(C[nt][0], C[nt][1], C[nt][2], C[nt][3],
                         Ah[0], Ah[1], Ah[2], Ah[3], Bh0, Bh1);
                    mma8(C[nt][0], C[nt][1], C[nt][2], C[nt][3],
                         Al[0], Al[1], Al[2], Al[3], Bh0, Bh1);
                    mma8(C[nt][0], C[nt][1], C[nt][2], C[nt][3],
                         Ah[0], Ah[1], Ah[2], Ah[3], Bl0, Bl1);
                }
            }
            #pragma unroll
            for (int nt = 0; nt < 4; ++nt) {
                int col = d0 + nt * 8 + 2 * c4;
                *reinterpret_cast<float2*>(&embB[(m0 + r8) * DD + col]) =
                    make_float2(C[nt][0], C[nt][1]);
                *reinterpret_cast<float2*>(&embB[(m0 + r8 + 8) * DD + col]) =
                    make_float2(C[nt][2], C[nt][3]);
            }
        }
    }

    // ========== nadj = S^T adj S, two 64-wide K chunks, plain tf32 ==========
    {
        float* nadjB = nadj + (size_t)b * NN * NN;
        for (int c = 0; c < 2; ++c) {
            const int ck = c * 64;
            __syncthreads();
            #pragma unroll
            for (int i = 0; i < 8; ++i) {          // stage adj chunk as tf32 u32
                int q   = tid + 256 * i;
                int row = q >> 4, cc = (q & 15) * 4;
                float4 v = *reinterpret_cast<const float4*>(&adjB[row * NN + ck + cc]);
                *reinterpret_cast<uint4*>(&Xa[row * XAR + cc]) =
                    make_uint4(tf32h(v.x), tf32h(v.y), tf32h(v.z), tf32h(v.w));
            }
            __syncthreads();

            // ---- Zc = S^T @ adjc : warp strip 16 x 64, 1 MMA per tile ----
            float Z[8][4];
            #pragma unroll
            for (int nt = 0; nt < 8; ++nt)
                #pragma unroll
                for (int q = 0; q < 4; ++q) Z[nt][q] = 0.f;
            for (int k8 = 0; k8 < 16; ++k8) {
                const int k0 = k8 * 8;
                u32t a0 = tf32h(sm.S[k0 + c4][m0 + r8]);
                u32t a1 = tf32h(sm.S[k0 + c4][m0 + r8 + 8]);
                u32t a2 = tf32h(sm.S[k0 + c4 + 4][m0 + r8]);
                u32t a3 = tf32h(sm.S[k0 + c4 + 4][m0 + r8 + 8]);
                #pragma unroll
                for (int nt = 0; nt < 8; ++nt) {
                    int n = nt * 8 + r8;
                    u32t b0 = Xa[(k0 + c4) * XAR + n];
                    u32t b1 = Xa[(k0 + c4 + 4) * XAR + n];
                    mma8(Z[nt][0], Z[nt][1], Z[nt][2], Z[nt][3],
                         a0, a1, a2, a3, b0, b1);
                }
            }
            __syncthreads();   // all reads of adjc done

            // store Zc rounded to tf32: Zcsm[m][i] (rows warp-private)
            #pragma unroll
            for (int nt = 0; nt < 8; ++nt) {
                int col = nt * 8 + 2 * c4;
                u64t w0 = (u64t)tf32h(Z[nt][0]) | ((u64t)tf32h(Z[nt][1]) << 32);
                u64t w1 = (u64t)tf32h(Z[nt][2]) | ((u64t)tf32h(Z[nt][3]) << 32);
                *reinterpret_cast<u64t*>(&Xa[(m0 + r8) * XAR + col])     = w0;
                *reinterpret_cast<u64t*>(&Xa[(m0 + r8 + 8) * XAR + col]) = w1;
            }
            __syncthreads();   // full Zc visible to all warps

            // ---- transposed partial: P = (S[ck:ck+64,:])^T-block x Zc^T ----
            // P[j, m] = sum_i S[ck+i][j] * Zc[m][i]  ( = nadj[m][j] partial )
            const int j0 = m0;
            float P[16][4];
            #pragma unroll
            for (int nt = 0; nt < 16; ++nt)
                #pragma unroll
                for (int q = 0; q < 4; ++q) P[nt][q] = 0.f;
            for (int k8 = 0; k8 < 8; ++k8) {
                const int k0 = k8 * 8;
                u32t a0 = tf32h(sm.S[ck + k0 + c4][j0 + r8]);
                u32t a1 = tf32h(sm.S[ck + k0 + c4][j0 + r8 + 8]);
                u32t a2 = tf32h(sm.S[ck + k0 + c4 + 4][j0 + r8]);
                u32t a3 = tf32h(sm.S[ck + k0 + c4 + 4][j0 + r8 + 8]);
                #pragma unroll
                for (int nt = 0; nt < 16; ++nt) {
                    int m = nt * 8 + r8;
                    u32t b0 = Xa[m * XAR + k0 + c4];
                    u32t b1 = Xa[m * XAR + k0 + c4 + 4];
                    mma8(P[nt][0], P[nt][1], P[nt][2], P[nt][3],
                         a0, a1, a2, a3, b0, b1);
                }
            }
            // scatter: P frag (row=j, col=m) -> nadj[m][j]
            #pragma unroll
            for (int nt = 0; nt < 16; ++nt) {
                int m = nt * 8 + 2 * c4;
                float* q0 = &nadjB[m * NN + j0 + r8];
                float* q1 = &nadjB[(m + 1) * NN + j0 + r8];
                float* q2 = &nadjB[m * NN + j0 + r8 + 8];
                float* q3 = &nadjB[(m + 1) * NN + j0 + r8 + 8];
                if (c == 0) {
                    *q0 = P[nt][0]; *q1 = P[nt][1]; *q2 = P[nt][2]; *q3 = P[nt][3];
                } else {
                    *q0 += P[nt][0]; *q1 += P[nt][1]; *q2 += P[nt][2]; *q3 += P[nt][3];
                }
            }
        }
    }
}

extern "C" void kernel_launch(void* const* d_in, const int* in_sizes, int n_in,
                              void* d_out, int out_size) {
    const float* x    = (const float*)d_in[0];   // concept_hidden [B,N,D]
    const float* adj  = (const float*)d_in[1];   // adj [B,N,N]
    const int*   head = (const int*)d_in[2];     // head [B,T]
    const float* lw   = (const float*)d_in[3];   // lin_w [1,D]
    const float* bias = (const float*)d_in[4];   // bias [1]

    float* out  = (float*)d_out;
    float* emb  = out;                                  // [B,N,D]
    float* nadj = out + (size_t)BB * NN * DD;           // [B,N,N]

    const int smemBytes = (int)sizeof(Smem);
    cudaFuncSetAttribute(graph_coarsen_kernel,
                         cudaFuncAttributeMaxDynamicSharedMemorySize, smemBytes);
    graph_coarsen_kernel<<<BB, 256, smemBytes>>>(x, adj, head, lw, bias, emb, nadj);
}